// round 13
// baseline (speedup 1.0000x reference)
#include <cuda_runtime.h>
#include <cuda_fp16.h>
#include <cstdint>

#define NODES 32768
#define KNB   12
#define DIM   128
#define ROWS  (NODES * KNB)          // 393216
#define TR1   64                     // K1 tile rows
#define NSUP  (ROWS / TR1)           // 6144
#define GRID1 304                    // 2 CTAs/SM

__device__ float g_logits[ROWS];

__device__ __forceinline__ uint32_t smem_u32(const void* p) {
    uint32_t a;
    asm("{ .reg .u64 t; cvta.to.shared.u64 t, %1; cvt.u32.u64 %0, t; }"
        : "=r"(a) : "l"(p));
    return a;
}

#define LDSM4(r, addr) \
    asm volatile("ldmatrix.sync.aligned.m8n8.x4.shared.b16 {%0,%1,%2,%3}, [%4];" \
        : "=r"((r)[0]), "=r"((r)[1]), "=r"((r)[2]), "=r"((r)[3]) : "r"(addr))

#define MMA_F16(acc, a, b) \
    asm volatile("mma.sync.aligned.m16n8k16.row.col.f32.f16.f16.f32 " \
        "{%0,%1,%2,%3}, {%4,%5,%6,%7}, {%8,%9}, {%0,%1,%2,%3};" \
        : "+f"((acc)[0]), "+f"((acc)[1]), "+f"((acc)[2]), "+f"((acc)[3]) \
        : "r"((a)[0]), "r"((a)[1]), "r"((a)[2]), "r"((a)[3]), \
          "r"((b)[0]), "r"((b)[1]))

#define BAR_SYNC(id)    asm volatile("bar.sync %0, 256;"   :: "r"(id) : "memory")
#define BAR_ARRIVE(id)  asm volatile("bar.arrive %0, 256;" :: "r"(id) : "memory")

__device__ __forceinline__ uint32_t sw_off(int row, int chunk) {
    return (uint32_t)(row * 256 + ((chunk ^ (row & 7)) << 4));
}

// ===========================================================================
// K1: logits = LeakyReLU(feat@w1 + wgt*w1bias)@w2
// 256 threads (2 CTAs/SM): warps 0-3 consumers (16 rows x 128 cols each),
// warps 4-7 producers. 64-row tiles, A triple-buffered.
// ===========================================================================
#define SM_W     0                  // w1^T fp16 (32KB)
#define SM_A0    32768              // A bufs 16KB each
#define SM_A1    49152
#define SM_A2    65536
#define SM_MISC  81920              // w1 bias [128] f32 | w2 [128] f32
#define SMEM1    (SM_MISC + 1024)

#define BAR_READY0 1
#define BAR_READY1 2
#define BAR_READY2 3
#define BAR_FREE0  4
#define BAR_FREE1  5
#define BAR_FREE2  6

extern "C" __global__ void __launch_bounds__(256, 2)
logits_kernel(const float* __restrict__ nbr,
              const float* __restrict__ wgt,
              const float* __restrict__ extra,
              const float* __restrict__ w1,
              const float* __restrict__ w2)
{
    extern __shared__ __align__(1024) char smem[];
    const int t    = threadIdx.x;
    const int lane = t & 31;
    const int w    = t >> 5;
    const uint32_t sb = smem_u32(smem);

    float* s_w1b = (float*)(smem + SM_MISC);
    float* s_w2  = s_w1b + 128;

    // ---- stage w1^T (Wt[n][k]) fp16, swizzled (once) ----
    #pragma unroll 4
    for (int i = 0; i < 64; ++i) {
        int idx = t + i * 256;                 // 16384 = 128*128
        int n = idx >> 7, k = idx & 127;
        __half hx = __float2half_rn(w1[k * 128 + n]);
        uint32_t off = sw_off(n, k >> 3) + (k & 7) * 2;
        asm volatile("st.shared.u16 [%0], %1;" :: "r"(sb + SM_W + off),
                     "h"(__half_as_ushort(hx)));
    }
    if (t < 128) { s_w1b[t] = w1[128 * 128 + t]; s_w2[t] = w2[t]; }
    __syncthreads();

    if (w >= 4) {
        // ================= PRODUCER (warps 4-7, 128 threads) =================
        const int pt = t - 128;
        const float4* nbr4   = (const float4*)nbr;
        const float4* extra4 = (const float4*)extra;
        int it = 0;
        for (int sup = blockIdx.x; sup < NSUP; sup += GRID1, ++it) {
            const int b = it % 3;
            if (it >= 3) BAR_SYNC(BAR_FREE0 + b);
            const uint32_t aBuf = sb + SM_A0 + b * 16384;
            const int row0 = sup * TR1;
            #pragma unroll 4
            for (int i = 0; i < 16; ++i) {
                int idx  = pt + i * 128;       // 2048 = 64 rows x 32 c4
                int row  = idx >> 5;
                int c4   = idx & 31;
                unsigned grow = (unsigned)(row0 + row);
                unsigned node = grow / KNB;
                float4 n = nbr4[(size_t)grow * 32 + c4];
                float4 e = extra4[(size_t)node * 32 + c4];
                float x0 = n.x * e.x, x1 = n.y * e.y, x2 = n.z * e.z, x3 = n.w * e.w;
                uint32_t p01, p23;
                asm("cvt.rn.f16x2.f32 %0, %1, %2;" : "=r"(p01) : "f"(x1), "f"(x0));
                asm("cvt.rn.f16x2.f32 %0, %1, %2;" : "=r"(p23) : "f"(x3), "f"(x2));
                uint32_t off = sw_off(row, c4 >> 1) + (c4 & 1) * 8;
                asm volatile("st.shared.v2.b32 [%0], {%1,%2};"
                             :: "r"(aBuf + off), "r"(p01), "r"(p23));
            }
            BAR_ARRIVE(BAR_READY0 + b);
        }
    } else {
        // ================= CONSUMER (warps 0-3, 128 threads) =================
        // warp w: rows [w*16, +16), full 128 cols (round-5 layout)
        const int aRow = (w << 4) + (lane & 15);
        const int aCb  = lane >> 4;
        const int aXor = aRow & 7;
        const int bNl  = ((lane >> 4) << 3) + (lane & 7);
        const int bCb  = (lane >> 3) & 1;

        int it = 0;
        for (int sup = blockIdx.x; sup < NSUP; sup += GRID1, ++it) {
            const int b = it % 3;
            BAR_SYNC(BAR_READY0 + b);
            const uint32_t aBase = sb + SM_A0 + b * 16384 + aRow * 256;
            const int row0 = sup * TR1;

            float acc[16][4];
            #pragma unroll
            for (int nt = 0; nt < 16; ++nt)
                { acc[nt][0] = acc[nt][1] = acc[nt][2] = acc[nt][3] = 0.f; }

            #pragma unroll
            for (int ks = 0; ks < 8; ++ks) {
                uint32_t ah[4];
                LDSM4(ah, aBase + (uint32_t)(((2 * ks + aCb) ^ aXor) << 4));
                #pragma unroll
                for (int j = 0; j < 8; ++j) {
                    int n = j * 16 + bNl;
                    uint32_t off = (uint32_t)(n * 256 + (((2 * ks + bCb) ^ (n & 7)) << 4));
                    uint32_t bh[4];
                    LDSM4(bh, sb + SM_W + off);
                    MMA_F16(acc[2*j],   ah, bh);
                    MMA_F16(acc[2*j+1], ah, bh + 2);
                }
            }
            BAR_ARRIVE(BAR_FREE0 + b);

            // ---- epilogue: bias + leaky_relu + dot(w2) + quad reduce ----
            const int grp = lane >> 2, qid = lane & 3;
            const int r0g = row0 + (w << 4) + grp;
            const int r1g = r0g + 8;
            const float wr0 = __ldg(&wgt[r0g]);
            const float wr1 = __ldg(&wgt[r1g]);
            float lg0 = 0.f, lg1 = 0.f;
            #pragma unroll
            for (int nt = 0; nt < 16; ++nt) {
                int c0 = nt * 8 + qid * 2;
                float b0 = s_w1b[c0], b1 = s_w1b[c0 + 1];
                float u0 = s_w2[c0],  u1 = s_w2[c0 + 1];
                float v;
                v = acc[nt][0] + wr0 * b0; v = (v >= 0.f) ? v : 0.2f * v; lg0 += v * u0;
                v = acc[nt][1] + wr0 * b1; v = (v >= 0.f) ? v : 0.2f * v; lg0 += v * u1;
                v = acc[nt][2] + wr1 * b0; v = (v >= 0.f) ? v : 0.2f * v; lg1 += v * u0;
                v = acc[nt][3] + wr1 * b1; v = (v >= 0.f) ? v : 0.2f * v; lg1 += v * u1;
            }
            lg0 += __shfl_xor_sync(0xffffffffu, lg0, 1);
            lg0 += __shfl_xor_sync(0xffffffffu, lg0, 2);
            lg1 += __shfl_xor_sync(0xffffffffu, lg1, 1);
            lg1 += __shfl_xor_sync(0xffffffffu, lg1, 2);
            if (qid == 0) { g_logits[r0g] = lg0; g_logits[r1g] = lg1; }
        }
    }
}

// ===========================================================================
// K23 fused, flat (round-9 structure), 256 threads, 64-node tiles, 2 CTAs/SM:
//   softmax(g_logits) -> p ; A = [fp16(self) | fp16(sum_k p*nbr)] ;
//   out = relu(A @ w3^T fp16).  GEMM: 8 warps x (16 rows x 64 cols).
// ===========================================================================
#define SM23_W  0                   // w3^T fp16 (64KB)
#define SM23_A  65536               // A fp16 tile 64x512B (32KB)
#define SM23_P  98304               // probs 64*12 f32 (3KB)
#define SMEM23  (98304 + 3072)
#define TR23    64
#define NT23    (NODES / TR23)      // 512 tiles

extern "C" __global__ void __launch_bounds__(256, 2)
fused_out_kernel(const float* __restrict__ nbr,
                 const float* __restrict__ selfv,
                 const float* __restrict__ w3,
                 float* __restrict__ out)
{
    extern __shared__ __align__(1024) char smem[];
    const int t    = threadIdx.x;
    const int lane = t & 31;
    const int w    = t >> 5;
    const uint32_t sb = smem_u32(smem);
    float* s_p = (float*)(smem + SM23_P);

    // ---- stage w3^T (Wt[n][k], k 0..255) fp16, swizzled (once) ----
    #pragma unroll 4
    for (int i = 0; i < 128; ++i) {
        int idx = t + i * 256;                 // 32768 = 256*128
        int n = idx >> 8, k = idx & 255;
        __half hx = __float2half_rn(w3[k * 128 + n]);
        uint32_t off = (uint32_t)(n * 512 + (((k >> 3) ^ (n & 7)) << 4) + (k & 7) * 2);
        asm volatile("st.shared.u16 [%0], %1;" :: "r"(sb + SM23_W + off),
                     "h"(__half_as_ushort(hx)));
    }

    const int wm = w & 3;                      // 4 row groups of 16
    const int wn = w >> 2;                     // 2 col groups of 64
    const int aRow = wm * 16 + (lane & 15);
    const int aCb  = lane >> 4;
    const int aXor = aRow & 7;
    const int bNl  = ((lane >> 4) << 3) + (lane & 7);
    const int bCb  = (lane >> 3) & 1;
    const uint32_t aBase = sb + SM23_A + aRow * 512;

    const float4* nbr4  = (const float4*)nbr;
    const float4* self4 = (const float4*)selfv;

    for (int tile = blockIdx.x; tile < NT23; tile += GRID1) {
        const int node0 = tile * TR23;
        __syncthreads();                        // A/probs safe to overwrite

        // ---- softmax for 64 nodes (threads 0..63) ----
        if (t < TR23) {
            const int base = (node0 + t) * KNB;
            float lg[KNB];
            float m = -1e30f;
            #pragma unroll
            for (int k = 0; k < KNB; ++k) { lg[k] = g_logits[base + k]; m = fmaxf(m, lg[k]); }
            float sum = 0.f;
            #pragma unroll
            for (int k = 0; k < KNB; ++k) { lg[k] = __expf(lg[k] - m); sum += lg[k]; }
            const float inv = 1.0f / sum;
            #pragma unroll
            for (int k = 0; k < KNB; ++k) s_p[t * KNB + k] = lg[k] * inv;
        }

        // ---- self -> A[k 0..127] (2048 units / 256 thr = 8 iters) ----
        #pragma unroll 4
        for (int i = 0; i < 8; ++i) {
            int idx = t + i * 256;
            int row = idx >> 5;
            int c4  = idx & 31;
            float4 v = self4[(size_t)(node0 + row) * 32 + c4];
            uint32_t p01, p23;
            asm("cvt.rn.f16x2.f32 %0, %1, %2;" : "=r"(p01) : "f"(v.y), "f"(v.x));
            asm("cvt.rn.f16x2.f32 %0, %1, %2;" : "=r"(p23) : "f"(v.w), "f"(v.z));
            uint32_t off = (uint32_t)(row * 512 + (((c4 >> 1) ^ (row & 7)) << 4)
                                      + (c4 & 1) * 8);
            asm volatile("st.shared.v2.b32 [%0], {%1,%2};"
                         :: "r"(sb + SM23_A + off), "r"(p01), "r"(p23));
        }
        __syncthreads();                        // probs ready

        // ---- agg -> A[k 128..255] (8 iters x 12 indep LDG.128) ----
        #pragma unroll 2
        for (int i = 0; i < 8; ++i) {
            int idx = t + i * 256;
            int row = idx >> 5;                 // node-local
            int c4  = idx & 31;
            const float* pp = s_p + row * KNB;
            const float4* nb = nbr4 + ((size_t)(node0 + row) * KNB) * 32 + c4;
            float4 agg = make_float4(0.f, 0.f, 0.f, 0.f);
            #pragma unroll
            for (int k = 0; k < KNB; ++k) {
                float pk = pp[k];
                float4 r = nb[k * 32];
                agg.x += pk * r.x; agg.y += pk * r.y;
                agg.z += pk * r.z; agg.w += pk * r.w;
            }
            uint32_t p01, p23;
            asm("cvt.rn.f16x2.f32 %0, %1, %2;" : "=r"(p01) : "f"(agg.y), "f"(agg.x));
            asm("cvt.rn.f16x2.f32 %0, %1, %2;" : "=r"(p23) : "f"(agg.w), "f"(agg.z));
            uint32_t off = (uint32_t)(row * 512 + ((((c4 >> 1) + 16) ^ (row & 7)) << 4)
                                      + (c4 & 1) * 8);
            asm volatile("st.shared.v2.b32 [%0], {%1,%2};"
                         :: "r"(sb + SM23_A + off), "r"(p01), "r"(p23));
        }
        __syncthreads();                        // A complete

        // ---- GEMM 64x128x256 fp16: 8 warps x (16 rows x 64 cols) ----
        float acc[8][4];
        #pragma unroll
        for (int ni = 0; ni < 8; ++ni)
            { acc[ni][0] = acc[ni][1] = acc[ni][2] = acc[ni][3] = 0.f; }

        #pragma unroll
        for (int ks = 0; ks < 16; ++ks) {
            uint32_t ah[4];
            LDSM4(ah, aBase + (uint32_t)(((2 * ks + aCb) ^ aXor) << 4));
            #pragma unroll
            for (int j = 0; j < 4; ++j) {
                int n = wn * 64 + j * 16 + bNl;
                uint32_t off = (uint32_t)(n * 512 + (((2 * ks + bCb) ^ (n & 7)) << 4));
                uint32_t bh[4];
                LDSM4(bh, sb + SM23_W + off);
                MMA_F16(acc[2*j],   ah, bh);
                MMA_F16(acc[2*j+1], ah, bh + 2);
            }
        }

        // ---- relu + store ----
        const int grp = lane >> 2, qid = lane & 3;
        const int rowg = node0 + wm * 16 + grp;
        #pragma unroll
        for (int ni = 0; ni < 8; ++ni) {
            int col = wn * 64 + ni * 8 + qid * 2;
            float2 o0, o1;
            o0.x = fmaxf(acc[ni][0], 0.f); o0.y = fmaxf(acc[ni][1], 0.f);
            o1.x = fmaxf(acc[ni][2], 0.f); o1.y = fmaxf(acc[ni][3], 0.f);
            *(float2*)(out + (size_t)rowg * 128 + col)       = o0;
            *(float2*)(out + (size_t)(rowg + 8) * 128 + col) = o1;
        }
    }
}

// ---------------------------------------------------------------------------
extern "C" void kernel_launch(void* const* d_in, const int* in_sizes, int n_in,
                              void* d_out, int out_size)
{
    int idx = 0;
    const float* selfv = (const float*)d_in[idx++];
    const float* nbr   = (const float*)d_in[idx++];
    if (idx < n_in && in_sizes[idx] == 1) idx++;   // batch_size scalar
    idx++;                                         // masks (unused)
    const float* wgt   = (const float*)d_in[idx++];
    const float* extra = (const float*)d_in[idx++];
    const float* w1    = (const float*)d_in[idx++];
    const float* w2    = (const float*)d_in[idx++];
    const float* w3    = (const float*)d_in[idx++];
    float* out = (float*)d_out;

    cudaFuncSetAttribute(logits_kernel,    cudaFuncAttributeMaxDynamicSharedMemorySize, SMEM1);
    cudaFuncSetAttribute(fused_out_kernel, cudaFuncAttributeMaxDynamicSharedMemorySize, SMEM23);

    logits_kernel<<<GRID1, 256, SMEM1>>>(nbr, wgt, extra, w1, w2);
    fused_out_kernel<<<GRID1, 256, SMEM23>>>(nbr, selfv, w3, out);
    (void)out_size; (void)n_in;
}

// round 14
// speedup vs baseline: 1.1751x; 1.1751x over previous
#include <cuda_runtime.h>
#include <cuda_fp16.h>
#include <cstdint>

#define NODES 32768
#define KNB   12
#define DIM   128
#define ROWS  (NODES * KNB)          // 393216
#define NSUP  (ROWS / 128)           // 3072
#define GRID1 152

__device__ float g_logits[ROWS];

__device__ __forceinline__ uint32_t smem_u32(const void* p) {
    uint32_t a;
    asm("{ .reg .u64 t; cvta.to.shared.u64 t, %1; cvt.u32.u64 %0, t; }"
        : "=r"(a) : "l"(p));
    return a;
}

#define LDSM4(r, addr) \
    asm volatile("ldmatrix.sync.aligned.m8n8.x4.shared.b16 {%0,%1,%2,%3}, [%4];" \
        : "=r"((r)[0]), "=r"((r)[1]), "=r"((r)[2]), "=r"((r)[3]) : "r"(addr))

#define MMA_F16(acc, a, b) \
    asm volatile("mma.sync.aligned.m16n8k16.row.col.f32.f16.f16.f32 " \
        "{%0,%1,%2,%3}, {%4,%5,%6,%7}, {%8,%9}, {%0,%1,%2,%3};" \
        : "+f"((acc)[0]), "+f"((acc)[1]), "+f"((acc)[2]), "+f"((acc)[3]) \
        : "r"((a)[0]), "r"((a)[1]), "r"((a)[2]), "r"((a)[3]), \
          "r"((b)[0]), "r"((b)[1]))

#define BAR_SYNC(id)    asm volatile("bar.sync %0, 512;"   :: "r"(id) : "memory")
#define BAR_ARRIVE(id)  asm volatile("bar.arrive %0, 512;" :: "r"(id) : "memory")
#define BAR_SYNC_C(id)  asm volatile("bar.sync %0, 256;"   :: "r"(id) : "memory")

__device__ __forceinline__ uint32_t sw_off(int row, int chunk) {
    return (uint32_t)(row * 256 + ((chunk ^ (row & 7)) << 4));
}

// ===========================================================================
// K1 (EXACT round-6 code, proven 85.3us): logits = LeakyReLU(feat@w1+...)@w2
// ===========================================================================
#define SM_W     0
#define SM_A0    32768
#define SM_A1    65536
#define SM_A2    98304
#define SM_MISC  131072
#define SMEM1    (SM_MISC + 512 + 512 + 1024)

#define BAR_READY0 1
#define BAR_READY1 2
#define BAR_READY2 3
#define BAR_FREE0  4
#define BAR_FREE1  5
#define BAR_FREE2  6
#define BAR_CONS   7

extern "C" __global__ void __launch_bounds__(512, 1)
logits_kernel(const float* __restrict__ nbr,
              const float* __restrict__ wgt,
              const float* __restrict__ extra,
              const float* __restrict__ w1,
              const float* __restrict__ w2)
{
    extern __shared__ __align__(1024) char smem[];
    const int t    = threadIdx.x;
    const int lane = t & 31;
    const int w    = t >> 5;
    const uint32_t sb = smem_u32(smem);

    float* s_w1b  = (float*)(smem + SM_MISC);
    float* s_w2   = s_w1b + 128;
    float* s_part = s_w2 + 128;

    #pragma unroll 4
    for (int i = 0; i < 32; ++i) {
        int idx = t + i * 512;
        int n = idx >> 7, k = idx & 127;
        __half hx = __float2half_rn(w1[k * 128 + n]);
        uint32_t off = sw_off(n, k >> 3) + (k & 7) * 2;
        asm volatile("st.shared.u16 [%0], %1;" :: "r"(sb + SM_W + off),
                     "h"(__half_as_ushort(hx)));
    }
    if (t < 128) { s_w1b[t] = w1[128 * 128 + t]; s_w2[t] = w2[t]; }
    __syncthreads();

    if (w >= 8) {
        const int pt = t & 255;
        const float4* nbr4   = (const float4*)nbr;
        const float4* extra4 = (const float4*)extra;
        int it = 0;
        for (int sup = blockIdx.x; sup < NSUP; sup += GRID1, ++it) {
            const int b = (it >= 3) ? (it % 3) : it;
            if (it >= 3) BAR_SYNC(BAR_FREE0 + b);
            const uint32_t aBuf = sb + SM_A0 + b * 32768;
            const int row0 = sup * 128;
            #pragma unroll 4
            for (int i = 0; i < 16; ++i) {
                int idx  = pt + i * 256;
                int row  = idx >> 5;
                int c4   = idx & 31;
                unsigned grow = (unsigned)(row0 + row);
                unsigned node = grow / KNB;
                float4 n = nbr4[(size_t)grow * 32 + c4];
                float4 e = extra4[(size_t)node * 32 + c4];
                float x0 = n.x * e.x, x1 = n.y * e.y, x2 = n.z * e.z, x3 = n.w * e.w;
                uint32_t p01, p23;
                asm("cvt.rn.f16x2.f32 %0, %1, %2;" : "=r"(p01) : "f"(x1), "f"(x0));
                asm("cvt.rn.f16x2.f32 %0, %1, %2;" : "=r"(p23) : "f"(x3), "f"(x2));
                uint32_t off = sw_off(row, c4 >> 1) + (c4 & 1) * 8;
                asm volatile("st.shared.v2.b32 [%0], {%1,%2};"
                             :: "r"(aBuf + off), "r"(p01), "r"(p23));
            }
            BAR_ARRIVE(BAR_READY0 + b);
        }
    } else {
        const int wm = w & 3;
        const int wn = w >> 2;
        const int aRow = wm * 32 + (lane & 15);
        const int aCb  = lane >> 4;
        const int aXor = aRow & 7;
        const int bNl  = ((lane >> 4) << 3) + (lane & 7);
        const int bCb  = (lane >> 3) & 1;
        const int bXor = lane & 7;
        const uint32_t nBase = (uint32_t)((wn * 64 + bNl) * 256);

        int it = 0;
        for (int sup = blockIdx.x; sup < NSUP; sup += GRID1, ++it) {
            const int b = (it >= 3) ? (it % 3) : it;
            BAR_SYNC(BAR_READY0 + b);
            const uint32_t aBase = sb + SM_A0 + b * 32768 + aRow * 256;
            const int row0 = sup * 128;

            float acc[2][8][4];
            #pragma unroll
            for (int mi = 0; mi < 2; ++mi)
                #pragma unroll
                for (int ni = 0; ni < 8; ++ni)
                    { acc[mi][ni][0]=acc[mi][ni][1]=acc[mi][ni][2]=acc[mi][ni][3]=0.f; }

            #pragma unroll
            for (int ks = 0; ks < 8; ++ks) {
                uint32_t a0[4], a1[4];
                uint32_t koffA = (uint32_t)(((2 * ks + aCb) ^ aXor) << 4);
                LDSM4(a0, aBase + koffA);
                LDSM4(a1, aBase + 4096 + koffA);
                uint32_t kc = (uint32_t)(((2 * ks + bCb) ^ bXor) << 4);
                #pragma unroll
                for (int j = 0; j < 4; ++j) {
                    uint32_t bh[4];
                    LDSM4(bh, sb + SM_W + nBase + (uint32_t)(j * 16 * 256) + kc);
                    MMA_F16(acc[0][2*j],   a0, bh);
                    MMA_F16(acc[0][2*j+1], a0, bh + 2);
                    MMA_F16(acc[1][2*j],   a1, bh);
                    MMA_F16(acc[1][2*j+1], a1, bh + 2);
                }
            }
            BAR_ARRIVE(BAR_FREE0 + b);

            const int grp = lane >> 2, qid = lane & 3;
            #pragma unroll
            for (int mi = 0; mi < 2; ++mi) {
                const int rowA = wm * 32 + mi * 16 + grp;
                const float wrA = __ldg(&wgt[row0 + rowA]);
                const float wrB = __ldg(&wgt[row0 + rowA + 8]);
                float pa = 0.f, pb = 0.f;
                #pragma unroll
                for (int ni = 0; ni < 8; ++ni) {
                    int c = wn * 64 + ni * 8 + qid * 2;
                    float b0 = s_w1b[c], b1 = s_w1b[c + 1];
                    float u0 = s_w2[c],  u1 = s_w2[c + 1];
                    float v;
                    v = acc[mi][ni][0] + wrA * b0; v = (v >= 0.f) ? v : 0.2f * v; pa += v * u0;
                    v = acc[mi][ni][1] + wrA * b1; v = (v >= 0.f) ? v : 0.2f * v; pa += v * u1;
                    v = acc[mi][ni][2] + wrB * b0; v = (v >= 0.f) ? v : 0.2f * v; pb += v * u0;
                    v = acc[mi][ni][3] + wrB * b1; v = (v >= 0.f) ? v : 0.2f * v; pb += v * u1;
                }
                pa += __shfl_xor_sync(0xffffffffu, pa, 1);
                pa += __shfl_xor_sync(0xffffffffu, pa, 2);
                pb += __shfl_xor_sync(0xffffffffu, pb, 1);
                pb += __shfl_xor_sync(0xffffffffu, pb, 2);
                if (qid == 0) {
                    s_part[rowA * 2 + wn]       = pa;
                    s_part[(rowA + 8) * 2 + wn] = pb;
                }
            }
            BAR_SYNC_C(BAR_CONS);
            if (wn == 0) {
                const int row = wm * 32 + lane;
                g_logits[row0 + row] = s_part[row * 2] + s_part[row * 2 + 1];
            }
            BAR_SYNC_C(BAR_CONS);
        }
    }
}

// ===========================================================================
// K23 fused, flat, 1024 threads (32 warps/SM): per 128-node tile:
//   softmax(g_logits) -> p ; A = [fp16(self) | fp16(sum_k p*nbr)] ;
//   out = relu(A @ w3^T fp16).  GEMM: 32 warps x (16 rows x 32 cols).
// ===========================================================================
#define SM23_W  0                   // w3^T fp16 (64KB)
#define SM23_A  65536               // A fp16 tile 128x512B (64KB)
#define SM23_P  131072              // probs 128*12 f32 (6KB)
#define SMEM23  (131072 + 6144)
#define NT23    (NODES / 128)       // 256 tiles

extern "C" __global__ void __launch_bounds__(1024, 1)
fused_out_kernel(const float* __restrict__ nbr,
                 const float* __restrict__ selfv,
                 const float* __restrict__ w3,
                 float* __restrict__ out)
{
    extern __shared__ __align__(1024) char smem[];
    const int t    = threadIdx.x;
    const int lane = t & 31;
    const int w    = t >> 5;                   // 0..31
    const uint32_t sb = smem_u32(smem);
    float* s_p = (float*)(smem + SM23_P);

    // ---- stage w3^T (Wt[n][k], k 0..255) fp16, swizzled (once) ----
    #pragma unroll 4
    for (int i = 0; i < 32; ++i) {
        int idx = t + i * 1024;                // 32768 = 256*128
        int n = idx >> 8, k = idx & 255;
        __half hx = __float2half_rn(w3[k * 128 + n]);
        uint32_t off = (uint32_t)(n * 512 + (((k >> 3) ^ (n & 7)) << 4) + (k & 7) * 2);
        asm volatile("st.shared.u16 [%0], %1;" :: "r"(sb + SM23_W + off),
                     "h"(__half_as_ushort(hx)));
    }
    __syncthreads();

    const int wm = w >> 2;                     // 0..7 : rows [wm*16, +16)
    const int wn = w & 3;                      // 0..3 : cols [wn*32, +32)
    const int aRow = wm * 16 + (lane & 15);
    const int aCb  = lane >> 4;
    const int aXor = aRow & 7;
    const int bNl  = ((lane >> 4) << 3) + (lane & 7);
    const int bCb  = (lane >> 3) & 1;
    const uint32_t aBase = sb + SM23_A + aRow * 512;

    const float4* nbr4  = (const float4*)nbr;
    const float4* self4 = (const float4*)selfv;

    for (int tile = blockIdx.x; tile < NT23; tile += GRID1) {
        const int node0 = tile * 128;
        __syncthreads();                        // A/probs safe to overwrite

        // ---- softmax for 128 nodes (threads 0..127) ----
        if (t < 128) {
            const int base = (node0 + t) * KNB;
            float lg[KNB];
            float m = -1e30f;
            #pragma unroll
            for (int k = 0; k < KNB; ++k) { lg[k] = g_logits[base + k]; m = fmaxf(m, lg[k]); }
            float sum = 0.f;
            #pragma unroll
            for (int k = 0; k < KNB; ++k) { lg[k] = __expf(lg[k] - m); sum += lg[k]; }
            const float inv = 1.0f / sum;
            #pragma unroll
            for (int k = 0; k < KNB; ++k) s_p[t * KNB + k] = lg[k] * inv;
        }

        // ---- self -> A[k 0..127] (4096 units / 1024 thr = 4 iters) ----
        #pragma unroll 4
        for (int i = 0; i < 4; ++i) {
            int idx = t + i * 1024;
            int row = idx >> 5;
            int c4  = idx & 31;
            float4 v = self4[(size_t)(node0 + row) * 32 + c4];
            uint32_t p01, p23;
            asm("cvt.rn.f16x2.f32 %0, %1, %2;" : "=r"(p01) : "f"(v.y), "f"(v.x));
            asm("cvt.rn.f16x2.f32 %0, %1, %2;" : "=r"(p23) : "f"(v.w), "f"(v.z));
            uint32_t off = (uint32_t)(row * 512 + (((c4 >> 1) ^ (row & 7)) << 4)
                                      + (c4 & 1) * 8);
            asm volatile("st.shared.v2.b32 [%0], {%1,%2};"
                         :: "r"(sb + SM23_A + off), "r"(p01), "r"(p23));
        }
        __syncthreads();                        // probs ready

        // ---- agg -> A[k 128..255] (4 iters x 12 indep LDG.128/thread) ----
        #pragma unroll 2
        for (int i = 0; i < 4; ++i) {
            int idx = t + i * 1024;
            int row = idx >> 5;                 // node-local (warp-uniform)
            int c4  = idx & 31;
            const float* pp = s_p + row * KNB;
            const float4* nb = nbr4 + ((size_t)(node0 + row) * KNB) * 32 + c4;
            float4 agg = make_float4(0.f, 0.f, 0.f, 0.f);
            #pragma unroll
            for (int k = 0; k < KNB; ++k) {
                float pk = pp[k];
                float4 r = nb[k * 32];
                agg.x += pk * r.x; agg.y += pk * r.y;
                agg.z += pk * r.z; agg.w += pk * r.w;
            }
            uint32_t p01, p23;
            asm("cvt.rn.f16x2.f32 %0, %1, %2;" : "=r"(p01) : "f"(agg.y), "f"(agg.x));
            asm("cvt.rn.f16x2.f32 %0, %1, %2;" : "=r"(p23) : "f"(agg.w), "f"(agg.z));
            uint32_t off = (uint32_t)(row * 512 + ((((c4 >> 1) + 16) ^ (row & 7)) << 4)
                                      + (c4 & 1) * 8);
            asm volatile("st.shared.v2.b32 [%0], {%1,%2};"
                         :: "r"(sb + SM23_A + off), "r"(p01), "r"(p23));
        }
        __syncthreads();                        // A complete

        // ---- GEMM 128x128x256 fp16: 32 warps x (16 rows x 32 cols) ----
        float acc[4][4];
        #pragma unroll
        for (int ni = 0; ni < 4; ++ni)
            { acc[ni][0] = acc[ni][1] = acc[ni][2] = acc[ni][3] = 0.f; }

        #pragma unroll
        for (int ks = 0; ks < 16; ++ks) {
            uint32_t ah[4];
            LDSM4(ah, aBase + (uint32_t)(((2 * ks + aCb) ^ aXor) << 4));
            #pragma unroll
            for (int j = 0; j < 2; ++j) {
                int n = wn * 32 + j * 16 + bNl;
                uint32_t off = (uint32_t)(n * 512 + (((2 * ks + bCb) ^ (n & 7)) << 4));
                uint32_t bh[4];
                LDSM4(bh, sb + SM23_W + off);
                MMA_F16(acc[2*j],   ah, bh);
                MMA_F16(acc[2*j+1], ah, bh + 2);
            }
        }

        // ---- relu + store ----
        const int grp = lane >> 2, qid = lane & 3;
        const int rowg = node0 + wm * 16 + grp;
        #pragma unroll
        for (int ni = 0; ni < 4; ++ni) {
            int col = wn * 32 + ni * 8 + qid * 2;
            float2 o0, o1;
            o0.x = fmaxf(acc[ni][0], 0.f); o0.y = fmaxf(acc[ni][1], 0.f);
            o1.x = fmaxf(acc[ni][2], 0.f); o1.y = fmaxf(acc[ni][3], 0.f);
            *(float2*)(out + (size_t)rowg * 128 + col)       = o0;
            *(float2*)(out + (size_t)(rowg + 8) * 128 + col) = o1;
        }
    }
}

// ---------------------------------------------------------------------------
extern "C" void kernel_launch(void* const* d_in, const int* in_sizes, int n_in,
                              void* d_out, int out_size)
{
    int idx = 0;
    const float* selfv = (const float*)d_in[idx++];
    const float* nbr   = (const float*)d_in[idx++];
    if (idx < n_in && in_sizes[idx] == 1) idx++;   // batch_size scalar
    idx++;                                         // masks (unused)
    const float* wgt   = (const float*)d_in[idx++];
    const float* extra = (const float*)d_in[idx++];
    const float* w1    = (const float*)d_in[idx++];
    const float* w2    = (const float*)d_in[idx++];
    const float* w3    = (const float*)d_in[idx++];
    float* out = (float*)d_out;

    cudaFuncSetAttribute(logits_kernel,    cudaFuncAttributeMaxDynamicSharedMemorySize, SMEM1);
    cudaFuncSetAttribute(fused_out_kernel, cudaFuncAttributeMaxDynamicSharedMemorySize, SMEM23);

    logits_kernel<<<GRID1, 512, SMEM1>>>(nbr, wgt, extra, w1, w2);
    fused_out_kernel<<<GRID1, 1024, SMEM23>>>(nbr, selfv, w3, out);
    (void)out_size; (void)n_in;
}